// round 12
// baseline (speedup 1.0000x reference)
#include <cuda_runtime.h>
#include <cuda_bf16.h>
#include <cstdint>

// Problem constants
#define Bv   32
#define Nv   128
#define Fv   78
#define Hv   256
#define Sv   20
#define Tv   13
#define Lv   3
#define ALPHA 0.2f
#define NEG_INF -9000000000000000.0f

#define BN (Bv*Nv)          // 4096 rows

// Scratch (device globals; no allocation allowed)
__device__ float g_xhi[(size_t)Hv*BN];        // x transposed [c][row], tf32 hi
__device__ float g_xlo[(size_t)Hv*BN];        // x transposed [c][row], tf32 lo
__device__ float g_hhi[(size_t)BN*Hv];        // projected h [row][c], tf32 hi
__device__ float g_hlo[(size_t)BN*Hv];        // projected h [row][c], tf32 lo
__device__ float g_whi[Lv*Hv*Hv];             // gat_W tf32 hi (all layers)
__device__ float g_wlo[Lv*Hv*Hv];             // gat_W tf32 lo
__device__ float g_zbuf[Lv*2*BN + Bv*Hv];     // s1/s2 per layer + graph accum

#define GRAPH_OFF (Lv*2*BN)

// ---------------------------------------------------------------------------
// helpers
// ---------------------------------------------------------------------------
__device__ __forceinline__ void tf32split(float v, float& hi, float& lo) {
    uint32_t u;
    asm("cvt.rna.tf32.f32 %0, %1;" : "=r"(u) : "f"(v));
    hi = __uint_as_float(u);
    float r = v - hi;
    asm("cvt.rna.tf32.f32 %0, %1;" : "=r"(u) : "f"(r));
    lo = __uint_as_float(u);
}

// cp.async helpers
__device__ __forceinline__ void cp16(uint32_t s, const void* g) {
    asm volatile("cp.async.ca.shared.global [%0], [%1], 16;" :: "r"(s), "l"(g));
}
#define CP_COMMIT() asm volatile("cp.async.commit_group;")
#define CP_WAIT1()  asm volatile("cp.async.wait_group 1;")
#define CP_WAIT0()  asm volatile("cp.async.wait_group 0;")

// tf32 mma m16n8k8 (A row-major, B col-major, fp32 accum)
#define MMA_TF32(C, A, B0, B1)                                                 \
    asm("mma.sync.aligned.m16n8k8.row.col.f32.tf32.tf32.f32 "                  \
        "{%0,%1,%2,%3}, {%4,%5,%6,%7}, {%8,%9}, {%0,%1,%2,%3};"                \
        : "+f"((C)[0]), "+f"((C)[1]), "+f"((C)[2]), "+f"((C)[3])               \
        : "r"((A)[0]), "r"((A)[1]), "r"((A)[2]), "r"((A)[3]),                  \
          "r"(B0), "r"(B1))

// ---------------------------------------------------------------------------
// K0: split gat_W into tf32 hi/lo for all layers
// ---------------------------------------------------------------------------
__global__ void k_split_w(const float* __restrict__ gat_W)
{
    int idx = blockIdx.x*256 + threadIdx.x;
    float v = gat_W[idx];
    float hi, lo;
    tf32split(v, hi, lo);
    g_whi[idx] = hi;
    g_wlo[idx] = lo;
}

// ---------------------------------------------------------------------------
// K1: x = node_features @ W_node + b_node -> g_xhi/g_xlo (transposed, split)
// ---------------------------------------------------------------------------
#define NP_ROWS 8
__global__ void k_node_proj(const float* __restrict__ nf,
                            const float* __restrict__ W,
                            const float* __restrict__ bias)
{
    int row0 = blockIdx.x * NP_ROWS;
    int j    = threadIdx.x;

    __shared__ __align__(16) float sf[Fv * NP_ROWS];   // [f][r]
    __shared__ float st[NP_ROWS * 257];                // transpose tile

    for (int idx = j; idx < Fv*NP_ROWS; idx += 256) {
        int f = idx >> 3, r = idx & 7;
        sf[idx] = nf[(row0 + r)*Fv + f];
    }
    __syncthreads();

    float bj = bias[j];
    float acc[NP_ROWS];
#pragma unroll
    for (int r = 0; r < NP_ROWS; ++r) acc[r] = bj;

#pragma unroll 6
    for (int f = 0; f < Fv; ++f) {
        float w = W[f*Hv + j];
        const float4* xp = reinterpret_cast<const float4*>(&sf[f*NP_ROWS]);
        float4 xa = xp[0], xb = xp[1];
        acc[0] += xa.x * w;  acc[1] += xa.y * w;
        acc[2] += xa.z * w;  acc[3] += xa.w * w;
        acc[4] += xb.x * w;  acc[5] += xb.y * w;
        acc[6] += xb.z * w;  acc[7] += xb.w * w;
    }

#pragma unroll
    for (int r = 0; r < NP_ROWS; ++r)
        st[r*257 + j] = acc[r];
    __syncthreads();
    int r  = j & 7;
    int cb = j >> 3;          // 0..31
#pragma unroll
    for (int p = 0; p < 8; ++p) {
        int c = cb + 32*p;
        float v = st[r*257 + c];
        float hi, lo;
        tf32split(v, hi, lo);
        g_xhi[(size_t)c*BN + row0 + r] = hi;
        g_xlo[(size_t)c*BN + row0 + r] = lo;
    }
}

// ---------------------------------------------------------------------------
// K2: h = x @ gat_W[l] via tf32 mma.sync (3-pass split) + partial scores.
// 128 threads = 4 warps; block tile 64 rows x 64 cols; warp tile 32x32.
// ---------------------------------------------------------------------------
#define PKC  16            // k per staged chunk
#define PSTR 72            // padded row length (conflict-free fragments)
__global__ void __launch_bounds__(128)
k_gat_proj(const float* __restrict__ a,   // [512] (a1 | a2)
           int layer)
{
    const int row0 = blockIdx.x * 64;
    const int c0   = blockIdx.y * 64;
    const int t    = threadIdx.x;
    const int w    = t >> 5, lane = t & 31;
    const int g    = lane >> 2, tid = lane & 3;
    const int row0w = (w & 1) * 32;
    const int col0w = (w >> 1) * 32;

    const float* xhi = g_xhi;
    const float* xlo = g_xlo;
    const float* whi = g_whi + (size_t)layer*Hv*Hv;
    const float* wlo = g_wlo + (size_t)layer*Hv*Hv;
    float* s1 = g_zbuf + layer*2*BN;
    float* s2 = s1 + BN;

    // smem: [buf][arr][k][PSTR]; arr: 0=xhi 1=xlo 2=whi 3=wlo
    __shared__ __align__(16) float sb[2][4][PKC*PSTR];
    const uint32_t sba = (uint32_t)__cvta_generic_to_shared(sb);

#define PISSUE(kc, buf)                                                        \
    {                                                                          \
        _Pragma("unroll")                                                      \
        for (int m = 0; m < 8; ++m) {                                          \
            const int arr = m >> 1;                                            \
            int sub = t + 128*(m & 1);      /* 0..255 */                       \
            int k = sub >> 4, f = sub & 15;                                    \
            uint32_t doff = sba + (((buf)*4 + arr)*(PKC*PSTR) + k*PSTR + f*4)*4; \
            const float* src;                                                  \
            if (arr == 0)      src = &xhi[(size_t)((kc)+k)*BN + row0 + f*4];   \
            else if (arr == 1) src = &xlo[(size_t)((kc)+k)*BN + row0 + f*4];   \
            else if (arr == 2) src = &whi[((kc)+k)*Hv + c0 + f*4];             \
            else               src = &wlo[((kc)+k)*Hv + c0 + f*4];             \
            cp16(doff, src);                                                   \
        }                                                                      \
        CP_COMMIT();                                                           \
    }

    float cacc[2][4][4];
#pragma unroll
    for (int mt = 0; mt < 2; ++mt)
#pragma unroll
        for (int nt = 0; nt < 4; ++nt)
#pragma unroll
            for (int q = 0; q < 4; ++q) cacc[mt][nt][q] = 0.f;

    PISSUE(0, 0);

    const int NCH = Hv / PKC;      // 16
#pragma unroll 4
    for (int c = 0; c < NCH; ++c) {
        const int cur = c & 1;
        if (c + 1 < NCH) {
            PISSUE((c+1)*PKC, (c+1)&1);
            CP_WAIT1();
        } else {
            CP_WAIT0();
        }
        __syncthreads();

        const float* sxh = sb[cur][0];
        const float* sxl = sb[cur][1];
        const float* swh = sb[cur][2];
        const float* swl = sb[cur][3];

#pragma unroll
        for (int ks = 0; ks < PKC; ks += 8) {
            uint32_t ah[2][4], al[2][4];
#pragma unroll
            for (int mt = 0; mt < 2; ++mt) {
                int rb = row0w + mt*16 + g;
                ah[mt][0] = __float_as_uint(sxh[(ks+tid)*PSTR + rb]);
                ah[mt][1] = __float_as_uint(sxh[(ks+tid)*PSTR + rb + 8]);
                ah[mt][2] = __float_as_uint(sxh[(ks+tid+4)*PSTR + rb]);
                ah[mt][3] = __float_as_uint(sxh[(ks+tid+4)*PSTR + rb + 8]);
                al[mt][0] = __float_as_uint(sxl[(ks+tid)*PSTR + rb]);
                al[mt][1] = __float_as_uint(sxl[(ks+tid)*PSTR + rb + 8]);
                al[mt][2] = __float_as_uint(sxl[(ks+tid+4)*PSTR + rb]);
                al[mt][3] = __float_as_uint(sxl[(ks+tid+4)*PSTR + rb + 8]);
            }
#pragma unroll
            for (int nt = 0; nt < 4; ++nt) {
                int cb = col0w + nt*8 + g;
                uint32_t bh0 = __float_as_uint(swh[(ks+tid)*PSTR + cb]);
                uint32_t bh1 = __float_as_uint(swh[(ks+tid+4)*PSTR + cb]);
                uint32_t bl0 = __float_as_uint(swl[(ks+tid)*PSTR + cb]);
                uint32_t bl1 = __float_as_uint(swl[(ks+tid+4)*PSTR + cb]);
#pragma unroll
                for (int mt = 0; mt < 2; ++mt) {
                    MMA_TF32(cacc[mt][nt], ah[mt], bh0, bh1);   // hi*hi
                    MMA_TF32(cacc[mt][nt], ah[mt], bl0, bl1);   // hi*lo
                    MMA_TF32(cacc[mt][nt], al[mt], bh0, bh1);   // lo*hi
                }
            }
        }
        __syncthreads();
    }
#undef PISSUE

    // epilogue: store h split (hi/lo), partial scores via quad-reduce + atomics
    float2 a1v[4], a2v[4];
#pragma unroll
    for (int nt = 0; nt < 4; ++nt) {
        a1v[nt] = *reinterpret_cast<const float2*>(&a[c0 + col0w + nt*8 + 2*tid]);
        a2v[nt] = *reinterpret_cast<const float2*>(&a[Hv + c0 + col0w + nt*8 + 2*tid]);
    }

#pragma unroll
    for (int mt = 0; mt < 2; ++mt) {
        int rA = row0 + row0w + mt*16 + g;
        int rB = rA + 8;
        float p1A = 0.f, p2A = 0.f, p1B = 0.f, p2B = 0.f;
#pragma unroll
        for (int nt = 0; nt < 4; ++nt) {
            float c0v = cacc[mt][nt][0], c1v = cacc[mt][nt][1];
            float c2v = cacc[mt][nt][2], c3v = cacc[mt][nt][3];
            int colb = c0 + col0w + nt*8 + 2*tid;
            float h0h, h0l, h1h, h1l, h2h, h2l, h3h, h3l;
            tf32split(c0v, h0h, h0l);  tf32split(c1v, h1h, h1l);
            tf32split(c2v, h2h, h2l);  tf32split(c3v, h3h, h3l);
            *reinterpret_cast<float2*>(&g_hhi[(size_t)rA*Hv + colb]) =
                make_float2(h0h, h1h);
            *reinterpret_cast<float2*>(&g_hlo[(size_t)rA*Hv + colb]) =
                make_float2(h0l, h1l);
            *reinterpret_cast<float2*>(&g_hhi[(size_t)rB*Hv + colb]) =
                make_float2(h2h, h3h);
            *reinterpret_cast<float2*>(&g_hlo[(size_t)rB*Hv + colb]) =
                make_float2(h2l, h3l);
            p1A += c0v*a1v[nt].x + c1v*a1v[nt].y;
            p2A += c0v*a2v[nt].x + c1v*a2v[nt].y;
            p1B += c2v*a1v[nt].x + c3v*a1v[nt].y;
            p2B += c2v*a2v[nt].x + c3v*a2v[nt].y;
        }
#pragma unroll
        for (int off = 1; off <= 2; off <<= 1) {
            p1A += __shfl_xor_sync(0xffffffffu, p1A, off);
            p2A += __shfl_xor_sync(0xffffffffu, p2A, off);
            p1B += __shfl_xor_sync(0xffffffffu, p1B, off);
            p2B += __shfl_xor_sync(0xffffffffu, p2B, off);
        }
        if (tid == 0) {
            atomicAdd(&s1[rA], p1A);  atomicAdd(&s2[rA], p2A);
            atomicAdd(&s1[rB], p1B);  atomicAdd(&s2[rB], p2B);
        }
    }
}

// ---------------------------------------------------------------------------
// K3: softmax + aggregation via tf32 mma.sync (3-pass split).
// 128 threads = 4 warps; block tile 64 i x 64 c; warp tile 32x32.
// att written hi/lo-split into smem [j][i]; h staged hi/lo via cp.async.
// Dynamic smem ~92.7 KB.
// ---------------------------------------------------------------------------
#define AST 72
#define AGG_SMEM ((2*Nv*AST + 2*2*16*AST + 128) * 4)
__global__ void __launch_bounds__(128)
k_gat_agg(const int* __restrict__ adj, int layer, int last)
{
    const int b  = blockIdx.z;
    const int i0 = blockIdx.x * 64;
    const int c0 = blockIdx.y * 64;
    const int t  = threadIdx.x;
    const int w  = t >> 5, lane = t & 31;
    const int g  = lane >> 2, tid = lane & 3;
    const int row0w = (w & 1) * 32;
    const int col0w = (w >> 1) * 32;

    const float* s1 = g_zbuf + layer*2*BN;
    const float* s2 = s1 + BN;

    extern __shared__ __align__(16) float dyn[];
    float* att_hi = dyn;                           // [j=128][AST]
    float* att_lo = dyn + Nv*AST;
    float* shbuf  = dyn + 2*Nv*AST;                // [buf][arr][16*AST]
    float* s2_sh  = shbuf + 2*2*16*AST;            // [128]
    const uint32_t shba = (uint32_t)__cvta_generic_to_shared(shbuf);

    const float* hhb = g_hhi + (size_t)b*Nv*Hv;
    const float* hlb = g_hlo + (size_t)b*Nv*Hv;

#define ISSUE_H(jc, buf)                                                       \
    {                                                                          \
        _Pragma("unroll")                                                      \
        for (int m = 0; m < 4; ++m) {                                          \
            const int arr = m >> 1;                                            \
            int sub = t + 128*(m & 1);      /* 0..255 */                       \
            int k = sub >> 4, f = sub & 15;                                    \
            uint32_t doff = shba + (((buf)*2 + arr)*(16*AST) + k*AST + f*4)*4; \
            const float* src = (arr == 0)                                      \
                ? &hhb[(size_t)((jc)+k)*Hv + c0 + f*4]                         \
                : &hlb[(size_t)((jc)+k)*Hv + c0 + f*4];                        \
            cp16(doff, src);                                                   \
        }                                                                      \
        CP_COMMIT();                                                           \
    }

    ISSUE_H(0, 0);       // overlap with softmax

    s2_sh[t] = s2[b*Nv + t];
    __syncthreads();

    // softmax: 16 rows per warp (4 warps x 16 = 64 rows); split att at write
#pragma unroll 4
    for (int rr = 0; rr < 16; ++rr) {
        int il = w*16 + rr;
        int i  = i0 + il;
        float s1i = s1[b*Nv + i];
        const int* adj_row = adj + (size_t)(b*Nv + i)*Nv;
        int4   am  = *reinterpret_cast<const int4*>(&adj_row[lane*4]);
        float4 s2v = *reinterpret_cast<const float4*>(&s2_sh[lane*4]);
        float e[4];
        {
            float v0 = s1i + s2v.x, v1 = s1i + s2v.y;
            float v2 = s1i + s2v.z, v3 = s1i + s2v.w;
            v0 = (v0 > 0.f) ? v0 : ALPHA*v0;  v1 = (v1 > 0.f) ? v1 : ALPHA*v1;
            v2 = (v2 > 0.f) ? v2 : ALPHA*v2;  v3 = (v3 > 0.f) ? v3 : ALPHA*v3;
            e[0] = (am.x > 0) ? v0 : NEG_INF;
            e[1] = (am.y > 0) ? v1 : NEG_INF;
            e[2] = (am.z > 0) ? v2 : NEG_INF;
            e[3] = (am.w > 0) ? v3 : NEG_INF;
        }
        float mx = fmaxf(fmaxf(e[0], e[1]), fmaxf(e[2], e[3]));
#pragma unroll
        for (int off = 16; off > 0; off >>= 1)
            mx = fmaxf(mx, __shfl_xor_sync(0xffffffffu, mx, off));
        float sum = 0.f;
#pragma unroll
        for (int q = 0; q < 4; ++q) { e[q] = __expf(e[q] - mx); sum += e[q]; }
#pragma unroll
        for (int off = 16; off > 0; off >>= 1)
            sum += __shfl_xor_sync(0xffffffffu, sum, off);
        float inv = 1.f / sum;
#pragma unroll
        for (int q = 0; q < 4; ++q) {
            float v = e[q] * inv;
            float hi, lo;
            tf32split(v, hi, lo);
            att_hi[(lane*4 + q)*AST + il] = hi;
            att_lo[(lane*4 + q)*AST + il] = lo;
        }
    }
    __syncthreads();   // att tiles complete before MMA reads

    float cacc[2][4][4];
#pragma unroll
    for (int mt = 0; mt < 2; ++mt)
#pragma unroll
        for (int nt = 0; nt < 4; ++nt)
#pragma unroll
            for (int q = 0; q < 4; ++q) cacc[mt][nt][q] = 0.f;

    const int NJC = Nv / 16;       // 8 chunks
#pragma unroll 4
    for (int c = 0; c < NJC; ++c) {
        const int cur = c & 1;
        if (c + 1 < NJC) {
            ISSUE_H((c+1)*16, (c+1)&1);
            CP_WAIT1();
        } else {
            CP_WAIT0();
        }
        __syncthreads();

        const float* shh = shbuf + cur*2*(16*AST);
        const float* shl = shh + 16*AST;

#pragma unroll
        for (int ks = 0; ks < 16; ks += 8) {
            int jb = c*16 + ks;          // global j base for A
            uint32_t ah[2][4], al[2][4];
#pragma unroll
            for (int mt = 0; mt < 2; ++mt) {
                int rb = row0w + mt*16 + g;
                ah[mt][0] = __float_as_uint(att_hi[(jb+tid)*AST + rb]);
                ah[mt][1] = __float_as_uint(att_hi[(jb+tid)*AST + rb + 8]);
                ah[mt][2] = __float_as_uint(att_hi[(jb+tid+4)*AST + rb]);
                ah[mt][3] = __float_as_uint(att_hi[(jb+tid+4)*AST + rb + 8]);
                al[mt][0] = __float_as_uint(att_lo[(jb+tid)*AST + rb]);
                al[mt][1] = __float_as_uint(att_lo[(jb+tid)*AST + rb + 8]);
                al[mt][2] = __float_as_uint(att_lo[(jb+tid+4)*AST + rb]);
                al[mt][3] = __float_as_uint(att_lo[(jb+tid+4)*AST + rb + 8]);
            }
#pragma unroll
            for (int nt = 0; nt < 4; ++nt) {
                int cb = col0w + nt*8 + g;
                uint32_t bh0 = __float_as_uint(shh[(ks+tid)*AST + cb]);
                uint32_t bh1 = __float_as_uint(shh[(ks+tid+4)*AST + cb]);
                uint32_t bl0 = __float_as_uint(shl[(ks+tid)*AST + cb]);
                uint32_t bl1 = __float_as_uint(shl[(ks+tid+4)*AST + cb]);
#pragma unroll
                for (int mt = 0; mt < 2; ++mt) {
                    MMA_TF32(cacc[mt][nt], ah[mt], bh0, bh1);   // hi*hi
                    MMA_TF32(cacc[mt][nt], ah[mt], bl0, bl1);   // hi*lo
                    MMA_TF32(cacc[mt][nt], al[mt], bh0, bh1);   // lo*hi
                }
            }
        }
        __syncthreads();
    }
#undef ISSUE_H

    if (last) {
        // fused mean partials: reduce relu over rows, atomics per column
        float* graph = g_zbuf + GRAPH_OFF;
#pragma unroll
        for (int nt = 0; nt < 4; ++nt) {
#pragma unroll
            for (int q2 = 0; q2 < 2; ++q2) {
                float p = fmaxf(cacc[0][nt][q2],   0.f)
                        + fmaxf(cacc[0][nt][q2+2], 0.f)
                        + fmaxf(cacc[1][nt][q2],   0.f)
                        + fmaxf(cacc[1][nt][q2+2], 0.f);
#pragma unroll
                for (int off = 4; off <= 16; off <<= 1)
                    p += __shfl_xor_sync(0xffffffffu, p, off);
                if (g == 0) {
                    int col = c0 + col0w + nt*8 + 2*tid + q2;
                    atomicAdd(&graph[b*Hv + col], p);
                }
            }
        }
    } else {
        // transpose relu through smem (reuse att_hi region: st[i][c], stride 68)
        float* st = att_hi;
#pragma unroll
        for (int mt = 0; mt < 2; ++mt) {
            int rowA = row0w + mt*16 + g;
            int rowB = rowA + 8;
#pragma unroll
            for (int nt = 0; nt < 4; ++nt) {
                int colb = col0w + nt*8 + 2*tid;
                st[rowA*68 + colb]     = fmaxf(cacc[mt][nt][0], 0.f);
                st[rowA*68 + colb + 1] = fmaxf(cacc[mt][nt][1], 0.f);
                st[rowB*68 + colb]     = fmaxf(cacc[mt][nt][2], 0.f);
                st[rowB*68 + colb + 1] = fmaxf(cacc[mt][nt][3], 0.f);
            }
        }
        __syncthreads();
        // thread t: channel ch = t&63, half = t>>6 -> 32 rows each, split store
        int ch   = t & 63;
        int half = t >> 6;
        size_t base = (size_t)(c0 + ch)*BN + b*Nv + i0 + half*32;
#pragma unroll
        for (int q = 0; q < 8; ++q) {
            int i = half*32 + 4*q;
            float4 hiv, lov;
            tf32split(st[(i+0)*68 + ch], hiv.x, lov.x);
            tf32split(st[(i+1)*68 + ch], hiv.y, lov.y);
            tf32split(st[(i+2)*68 + ch], hiv.z, lov.z);
            tf32split(st[(i+3)*68 + ch], hiv.w, lov.w);
            *reinterpret_cast<float4*>(&g_xhi[base + 4*q]) = hiv;
            *reinterpret_cast<float4*>(&g_xlo[base + 4*q]) = lov;
        }
    }
}

// ---------------------------------------------------------------------------
// K5: fused head. One block per batch element.
// ---------------------------------------------------------------------------
__global__ void k_head(const float* __restrict__ scaffold,
                       const float* __restrict__ W_sc,
                       const float* __restrict__ b_sc,
                       const float* __restrict__ gp_w1,
                       const float* __restrict__ gp_b1,
                       const float* __restrict__ gp_w2,
                       const float* __restrict__ gp_b2,
                       const float* __restrict__ out_w1,
                       const float* __restrict__ out_b1,
                       const float* __restrict__ out_w2,
                       const float* __restrict__ out_b2,
                       float* __restrict__ out)
{
    int b = blockIdx.x, t = threadIdx.x;
    const float* graph = g_zbuf + GRAPH_OFF;
    __shared__ float scaf[Sv];
    __shared__ float grow[Hv];
    __shared__ float sc[Hv];
    __shared__ float g1[128], sp1[128];
    __shared__ float c[128];
    __shared__ float hdn[128];

    if (t < Sv) scaf[t] = scaffold[b*Sv + t];
    grow[t] = graph[b*Hv + t] * (1.0f/Nv);
    __syncthreads();

    {
        float acc = b_sc[t];
#pragma unroll
        for (int k = 0; k < Sv; ++k)
            acc += scaf[k] * W_sc[k*Hv + t];
        sc[t] = acc;
    }
    __syncthreads();

    {
        int col = t & 127;
        const float* src = (t < 128) ? grow : sc;
        float acc = gp_b1[col];
#pragma unroll 4
        for (int k = 0; k < Hv; ++k)
            acc += src[k] * gp_w1[k*128 + col];
        acc = fmaxf(acc, 0.f);
        if (t < 128) g1[col] = acc; else sp1[col] = acc;
    }
    __syncthreads();

    if (t < 128) {
        int col = t & 63;
        const float* src = (t < 64) ? g1 : sp1;
        float acc = gp_b2[col];
#pragma unroll 4
        for (int k = 0; k < 128; ++k)
            acc += src[k] * gp_w2[k*64 + col];
        c[t] = fmaxf(acc, 0.f);
    }
    __syncthreads();

    if (t < 128) {
        float acc = out_b1[t];
#pragma unroll 4
        for (int k = 0; k < 128; ++k)
            acc += c[k] * out_w1[k*128 + t];
        hdn[t] = fmaxf(acc, 0.f);
    }
    __syncthreads();

    if (t < Tv) {
        float acc = out_b2[t];
#pragma unroll 4
        for (int k = 0; k < 128; ++k)
            acc += hdn[k] * out_w2[k*Tv + t];
        out[b*Tv + t] = acc;
    }
}

// ---------------------------------------------------------------------------
extern "C" void kernel_launch(void* const* d_in, const int* in_sizes, int n_in,
                              void* d_out, int out_size)
{
    const float* node_features     = (const float*)d_in[0];
    // d_in[1] = edge_features — unused by the reference
    const int*   adj_matrix        = (const int*)  d_in[2];
    const float* scaffold_features = (const float*)d_in[3];
    const float* W_node            = (const float*)d_in[4];
    const float* b_node            = (const float*)d_in[5];
    const float* gat_W             = (const float*)d_in[6];
    const float* gat_a             = (const float*)d_in[7];
    const float* W_sc              = (const float*)d_in[8];
    const float* b_sc              = (const float*)d_in[9];
    const float* gp_w1             = (const float*)d_in[10];
    const float* gp_b1             = (const float*)d_in[11];
    const float* gp_w2             = (const float*)d_in[12];
    const float* gp_b2             = (const float*)d_in[13];
    const float* out_w1            = (const float*)d_in[14];
    const float* out_b1            = (const float*)d_in[15];
    const float* out_w2            = (const float*)d_in[16];
    const float* out_b2            = (const float*)d_in[17];
    float* out = (float*)d_out;

    cudaFuncSetAttribute(k_gat_agg,
                         cudaFuncAttributeMaxDynamicSharedMemorySize, AGG_SMEM);

    void* zp = nullptr;
    cudaGetSymbolAddress(&zp, g_zbuf);
    cudaMemsetAsync(zp, 0, (Lv*2*BN + Bv*Hv)*sizeof(float));

    k_split_w<<<Lv*Hv*Hv/256, 256>>>(gat_W);
    k_node_proj<<<BN/NP_ROWS, 256>>>(node_features, W_node, b_node);

    for (int l = 0; l < Lv; ++l) {
        dim3 pg(BN/64, Hv/64);                 // 64 x 4 = 256 blocks, 128 thr
        k_gat_proj<<<pg, 128>>>(gat_a + (size_t)l*2*Hv, l);
        dim3 ag(Nv/64, Hv/64, Bv);             // 2 x 4 x 32 = 256 blocks, 128 thr
        k_gat_agg<<<ag, 128, AGG_SMEM>>>(adj_matrix, l, l == Lv-1);
    }

    k_head<<<Bv, 256>>>(scaffold_features, W_sc, b_sc,
                        gp_w1, gp_b1, gp_w2, gp_b2,
                        out_w1, out_b1, out_w2, out_b2, out);
}

// round 13
// speedup vs baseline: 1.2699x; 1.2699x over previous
#include <cuda_runtime.h>
#include <cuda_bf16.h>
#include <cstdint>

// Problem constants
#define Bv   32
#define Nv   128
#define Fv   78
#define Hv   256
#define Sv   20
#define Tv   13
#define Lv   3
#define ALPHA 0.2f
#define NEG_INF -9000000000000000.0f

#define BN (Bv*Nv)          // 4096 rows

// Scratch (device globals; no allocation allowed)
__device__ float g_xhi[(size_t)Hv*BN];        // x transposed [c][row], tf32 hi
__device__ float g_xlo[(size_t)Hv*BN];        // x transposed [c][row], tf32 lo
__device__ float g_hhi[(size_t)BN*Hv];        // projected h [row][c], tf32 hi
__device__ float g_hlo[(size_t)BN*Hv];        // projected h [row][c], tf32 lo
__device__ float g_whi[Lv*Hv*Hv];             // gat_W tf32 hi (all layers)
__device__ float g_wlo[Lv*Hv*Hv];             // gat_W tf32 lo
__device__ float g_zbuf[Lv*2*BN + Bv*Hv];     // s1/s2 per layer + graph accum

#define GRAPH_OFF (Lv*2*BN)

// ---------------------------------------------------------------------------
// helpers
// ---------------------------------------------------------------------------
__device__ __forceinline__ void tf32split(float v, float& hi, float& lo) {
    uint32_t u;
    asm("cvt.rna.tf32.f32 %0, %1;" : "=r"(u) : "f"(v));
    hi = __uint_as_float(u);
    float r = v - hi;
    asm("cvt.rna.tf32.f32 %0, %1;" : "=r"(u) : "f"(r));
    lo = __uint_as_float(u);
}

// cp.async helpers
__device__ __forceinline__ void cp16(uint32_t s, const void* g) {
    asm volatile("cp.async.ca.shared.global [%0], [%1], 16;" :: "r"(s), "l"(g));
}
#define CP_COMMIT() asm volatile("cp.async.commit_group;")
#define CP_WAIT1()  asm volatile("cp.async.wait_group 1;")
#define CP_WAIT0()  asm volatile("cp.async.wait_group 0;")

// tf32 mma m16n8k8 (A row-major, B col-major, fp32 accum)
#define MMA_TF32(C, A, B0, B1)                                                 \
    asm("mma.sync.aligned.m16n8k8.row.col.f32.tf32.tf32.f32 "                  \
        "{%0,%1,%2,%3}, {%4,%5,%6,%7}, {%8,%9}, {%0,%1,%2,%3};"                \
        : "+f"((C)[0]), "+f"((C)[1]), "+f"((C)[2]), "+f"((C)[3])               \
        : "r"((A)[0]), "r"((A)[1]), "r"((A)[2]), "r"((A)[3]),                  \
          "r"(B0), "r"(B1))

// ---------------------------------------------------------------------------
// K0: split gat_W into tf32 hi/lo for all layers
// ---------------------------------------------------------------------------
__global__ void k_split_w(const float* __restrict__ gat_W)
{
    int idx = blockIdx.x*256 + threadIdx.x;
    float v = gat_W[idx];
    float hi, lo;
    tf32split(v, hi, lo);
    g_whi[idx] = hi;
    g_wlo[idx] = lo;
}

// ---------------------------------------------------------------------------
// K1: x = node_features @ W_node + b_node -> g_xhi/g_xlo (transposed, split)
// ---------------------------------------------------------------------------
#define NP_ROWS 8
__global__ void k_node_proj(const float* __restrict__ nf,
                            const float* __restrict__ W,
                            const float* __restrict__ bias)
{
    int row0 = blockIdx.x * NP_ROWS;
    int j    = threadIdx.x;

    __shared__ __align__(16) float sf[Fv * NP_ROWS];   // [f][r]
    __shared__ float st[NP_ROWS * 257];                // transpose tile

    for (int idx = j; idx < Fv*NP_ROWS; idx += 256) {
        int f = idx >> 3, r = idx & 7;
        sf[idx] = nf[(row0 + r)*Fv + f];
    }
    __syncthreads();

    float bj = bias[j];
    float acc[NP_ROWS];
#pragma unroll
    for (int r = 0; r < NP_ROWS; ++r) acc[r] = bj;

#pragma unroll 6
    for (int f = 0; f < Fv; ++f) {
        float w = W[f*Hv + j];
        const float4* xp = reinterpret_cast<const float4*>(&sf[f*NP_ROWS]);
        float4 xa = xp[0], xb = xp[1];
        acc[0] += xa.x * w;  acc[1] += xa.y * w;
        acc[2] += xa.z * w;  acc[3] += xa.w * w;
        acc[4] += xb.x * w;  acc[5] += xb.y * w;
        acc[6] += xb.z * w;  acc[7] += xb.w * w;
    }

#pragma unroll
    for (int r = 0; r < NP_ROWS; ++r)
        st[r*257 + j] = acc[r];
    __syncthreads();
    int r  = j & 7;
    int cb = j >> 3;          // 0..31
#pragma unroll
    for (int p = 0; p < 8; ++p) {
        int c = cb + 32*p;
        float v = st[r*257 + c];
        float hi, lo;
        tf32split(v, hi, lo);
        g_xhi[(size_t)c*BN + row0 + r] = hi;
        g_xlo[(size_t)c*BN + row0 + r] = lo;
    }
}

// ---------------------------------------------------------------------------
// K2: h = x @ gat_W[l] via tf32 mma.sync (3-pass split) + partial scores.
// 128 threads = 4 warps; block tile 32 rows x 64 cols; warp tile 16x32.
// grid = (BN/32, Hv/64) = 512 blocks.
// ---------------------------------------------------------------------------
#define XSTR 40            // x tile row stride
#define WSTR 72            // w tile row stride
__global__ void __launch_bounds__(128)
k_gat_proj(const float* __restrict__ a,   // [512] (a1 | a2)
           int layer)
{
    const int row0 = blockIdx.x * 32;
    const int c0   = blockIdx.y * 64;
    const int t    = threadIdx.x;
    const int w    = t >> 5, lane = t & 31;
    const int g    = lane >> 2, tid = lane & 3;
    const int row0w = (w & 1) * 16;
    const int col0w = (w >> 1) * 32;

    const float* xhi = g_xhi;
    const float* xlo = g_xlo;
    const float* whi = g_whi + (size_t)layer*Hv*Hv;
    const float* wlo = g_wlo + (size_t)layer*Hv*Hv;
    float* s1 = g_zbuf + layer*2*BN;
    float* s2 = s1 + BN;

    __shared__ __align__(16) float sx[2][2][16*XSTR];  // [buf][hi/lo]
    __shared__ __align__(16) float sw[2][2][16*WSTR];
    const uint32_t sxa = (uint32_t)__cvta_generic_to_shared(sx);
    const uint32_t swa = (uint32_t)__cvta_generic_to_shared(sw);

    // x: per array 16k x 8 float4-pieces = 128 (one per thread)
    // w: per array 16k x 16 pieces = 256 (two per thread)
#define PISSUE(kc, buf)                                                        \
    {                                                                          \
        _Pragma("unroll")                                                      \
        for (int m = 0; m < 2; ++m) {                                          \
            int k = t >> 3, f = t & 7;                                         \
            uint32_t doff = sxa + (((buf)*2 + m)*(16*XSTR) + k*XSTR + f*4)*4;  \
            const float* src = m ? &xlo[(size_t)((kc)+k)*BN + row0 + f*4]      \
                                 : &xhi[(size_t)((kc)+k)*BN + row0 + f*4];     \
            cp16(doff, src);                                                   \
        }                                                                      \
        _Pragma("unroll")                                                      \
        for (int m = 0; m < 4; ++m) {                                          \
            const int arr = m >> 1;                                            \
            int sub = t + 128*(m & 1);                                         \
            int k = sub >> 4, f = sub & 15;                                    \
            uint32_t doff = swa + (((buf)*2 + arr)*(16*WSTR) + k*WSTR + f*4)*4; \
            const float* src = arr ? &wlo[((kc)+k)*Hv + c0 + f*4]              \
                                   : &whi[((kc)+k)*Hv + c0 + f*4];             \
            cp16(doff, src);                                                   \
        }                                                                      \
        CP_COMMIT();                                                           \
    }

    float cacc[4][4];
#pragma unroll
    for (int nt = 0; nt < 4; ++nt)
#pragma unroll
        for (int q = 0; q < 4; ++q) cacc[nt][q] = 0.f;

    PISSUE(0, 0);

    const int NCH = Hv / 16;       // 16 chunks
#pragma unroll 4
    for (int c = 0; c < NCH; ++c) {
        const int cur = c & 1;
        if (c + 1 < NCH) {
            PISSUE((c+1)*16, (c+1)&1);
            CP_WAIT1();
        } else {
            CP_WAIT0();
        }
        __syncthreads();

        const float* sxh = sx[cur][0];
        const float* sxl = sx[cur][1];
        const float* swh = sw[cur][0];
        const float* swl = sw[cur][1];

#pragma unroll
        for (int ks = 0; ks < 16; ks += 8) {
            uint32_t ah[4], al[4];
            int rb = row0w + g;
            ah[0] = __float_as_uint(sxh[(ks+tid)*XSTR + rb]);
            ah[1] = __float_as_uint(sxh[(ks+tid)*XSTR + rb + 8]);
            ah[2] = __float_as_uint(sxh[(ks+tid+4)*XSTR + rb]);
            ah[3] = __float_as_uint(sxh[(ks+tid+4)*XSTR + rb + 8]);
            al[0] = __float_as_uint(sxl[(ks+tid)*XSTR + rb]);
            al[1] = __float_as_uint(sxl[(ks+tid)*XSTR + rb + 8]);
            al[2] = __float_as_uint(sxl[(ks+tid+4)*XSTR + rb]);
            al[3] = __float_as_uint(sxl[(ks+tid+4)*XSTR + rb + 8]);
#pragma unroll
            for (int nt = 0; nt < 4; ++nt) {
                int cb = col0w + nt*8 + g;
                uint32_t bh0 = __float_as_uint(swh[(ks+tid)*WSTR + cb]);
                uint32_t bh1 = __float_as_uint(swh[(ks+tid+4)*WSTR + cb]);
                uint32_t bl0 = __float_as_uint(swl[(ks+tid)*WSTR + cb]);
                uint32_t bl1 = __float_as_uint(swl[(ks+tid+4)*WSTR + cb]);
                MMA_TF32(cacc[nt], ah, bh0, bh1);   // hi*hi
                MMA_TF32(cacc[nt], ah, bl0, bl1);   // hi*lo
                MMA_TF32(cacc[nt], al, bh0, bh1);   // lo*hi
            }
        }
        __syncthreads();
    }
#undef PISSUE

    // epilogue: store h split, partial scores via quad-reduce + atomics
    float2 a1v[4], a2v[4];
#pragma unroll
    for (int nt = 0; nt < 4; ++nt) {
        a1v[nt] = *reinterpret_cast<const float2*>(&a[c0 + col0w + nt*8 + 2*tid]);
        a2v[nt] = *reinterpret_cast<const float2*>(&a[Hv + c0 + col0w + nt*8 + 2*tid]);
    }

    int rA = row0 + row0w + g;
    int rB = rA + 8;
    float p1A = 0.f, p2A = 0.f, p1B = 0.f, p2B = 0.f;
#pragma unroll
    for (int nt = 0; nt < 4; ++nt) {
        float c0v = cacc[nt][0], c1v = cacc[nt][1];
        float c2v = cacc[nt][2], c3v = cacc[nt][3];
        int colb = c0 + col0w + nt*8 + 2*tid;
        float h0h, h0l, h1h, h1l, h2h, h2l, h3h, h3l;
        tf32split(c0v, h0h, h0l);  tf32split(c1v, h1h, h1l);
        tf32split(c2v, h2h, h2l);  tf32split(c3v, h3h, h3l);
        *reinterpret_cast<float2*>(&g_hhi[(size_t)rA*Hv + colb]) = make_float2(h0h, h1h);
        *reinterpret_cast<float2*>(&g_hlo[(size_t)rA*Hv + colb]) = make_float2(h0l, h1l);
        *reinterpret_cast<float2*>(&g_hhi[(size_t)rB*Hv + colb]) = make_float2(h2h, h3h);
        *reinterpret_cast<float2*>(&g_hlo[(size_t)rB*Hv + colb]) = make_float2(h2l, h3l);
        p1A += c0v*a1v[nt].x + c1v*a1v[nt].y;
        p2A += c0v*a2v[nt].x + c1v*a2v[nt].y;
        p1B += c2v*a1v[nt].x + c3v*a1v[nt].y;
        p2B += c2v*a2v[nt].x + c3v*a2v[nt].y;
    }
#pragma unroll
    for (int off = 1; off <= 2; off <<= 1) {
        p1A += __shfl_xor_sync(0xffffffffu, p1A, off);
        p2A += __shfl_xor_sync(0xffffffffu, p2A, off);
        p1B += __shfl_xor_sync(0xffffffffu, p1B, off);
        p2B += __shfl_xor_sync(0xffffffffu, p2B, off);
    }
    if (tid == 0) {
        atomicAdd(&s1[rA], p1A);  atomicAdd(&s2[rA], p2A);
        atomicAdd(&s1[rB], p1B);  atomicAdd(&s2[rB], p2B);
    }
}

// ---------------------------------------------------------------------------
// K3: softmax + aggregation via tf32 mma.sync (3-pass, att split at load).
// 128 threads = 4 warps; block tile 32 i x 64 c; warp tile 16x32.
// grid = (Nv/32, Hv/64, Bv) = 512 blocks. Static smem ~37.4 KB.
// ---------------------------------------------------------------------------
#define SATT 36
__global__ void __launch_bounds__(128)
k_gat_agg(const int* __restrict__ adj, int layer, int last)
{
    const int b  = blockIdx.z;
    const int i0 = blockIdx.x * 32;
    const int c0 = blockIdx.y * 64;
    const int t  = threadIdx.x;
    const int w  = t >> 5, lane = t & 31;
    const int g  = lane >> 2, tid = lane & 3;
    const int row0w = (w & 1) * 16;
    const int col0w = (w >> 1) * 32;

    const float* s1 = g_zbuf + layer*2*BN;
    const float* s2 = s1 + BN;

    __shared__ __align__(16) float att[Nv*SATT];       // fp32 att [j][i_local]
    __shared__ __align__(16) float sh[2][2][16*WSTR];  // h chunks hi/lo
    __shared__ float s2_sh[Nv];
    const uint32_t sha = (uint32_t)__cvta_generic_to_shared(sh);

    const float* hhb = g_hhi + (size_t)b*Nv*Hv;
    const float* hlb = g_hlo + (size_t)b*Nv*Hv;

#define ISSUE_H(jc, buf)                                                       \
    {                                                                          \
        _Pragma("unroll")                                                      \
        for (int m = 0; m < 4; ++m) {                                          \
            const int arr = m >> 1;                                            \
            int sub = t + 128*(m & 1);                                         \
            int k = sub >> 4, f = sub & 15;                                    \
            uint32_t doff = sha + (((buf)*2 + arr)*(16*WSTR) + k*WSTR + f*4)*4; \
            const float* src = arr ? &hlb[(size_t)((jc)+k)*Hv + c0 + f*4]      \
                                   : &hhb[(size_t)((jc)+k)*Hv + c0 + f*4];     \
            cp16(doff, src);                                                   \
        }                                                                      \
        CP_COMMIT();                                                           \
    }

    ISSUE_H(0, 0);       // overlap with softmax

    s2_sh[t] = s2[b*Nv + t];
    __syncthreads();

    // softmax: 8 rows per warp (4 warps x 8 = 32 rows); j = lane + q*32
#pragma unroll
    for (int rr = 0; rr < 8; ++rr) {
        int il = w*8 + rr;
        int i  = i0 + il;
        float s1i = s1[b*Nv + i];
        const int* adj_row = adj + (size_t)(b*Nv + i)*Nv;
        float e[4];
        float mx = NEG_INF;
#pragma unroll
        for (int q = 0; q < 4; ++q) {
            int jj = lane + q*32;
            float v = s1i + s2_sh[jj];
            v = (v > 0.f) ? v : ALPHA * v;
            v = (adj_row[jj] > 0) ? v : NEG_INF;
            e[q] = v;
            mx = fmaxf(mx, v);
        }
#pragma unroll
        for (int off = 16; off > 0; off >>= 1)
            mx = fmaxf(mx, __shfl_xor_sync(0xffffffffu, mx, off));
        float sum = 0.f;
#pragma unroll
        for (int q = 0; q < 4; ++q) { e[q] = __expf(e[q] - mx); sum += e[q]; }
#pragma unroll
        for (int off = 16; off > 0; off >>= 1)
            sum += __shfl_xor_sync(0xffffffffu, sum, off);
        float inv = 1.f / sum;
#pragma unroll
        for (int q = 0; q < 4; ++q)
            att[(lane + q*32)*SATT + il] = e[q] * inv;
    }
    __syncthreads();

    float cacc[4][4];
#pragma unroll
    for (int nt = 0; nt < 4; ++nt)
#pragma unroll
        for (int q = 0; q < 4; ++q) cacc[nt][q] = 0.f;

    const int NJC = Nv / 16;       // 8 chunks
#pragma unroll 4
    for (int c = 0; c < NJC; ++c) {
        const int cur = c & 1;
        if (c + 1 < NJC) {
            ISSUE_H((c+1)*16, (c+1)&1);
            CP_WAIT1();
        } else {
            CP_WAIT0();
        }
        __syncthreads();

        const float* shh = sh[cur][0];
        const float* shl = sh[cur][1];

#pragma unroll
        for (int ks = 0; ks < 16; ks += 8) {
            int jb = c*16 + ks;
            int rb = row0w + g;
            float av[4];
            av[0] = att[(jb+tid)*SATT + rb];
            av[1] = att[(jb+tid)*SATT + rb + 8];
            av[2] = att[(jb+tid+4)*SATT + rb];
            av[3] = att[(jb+tid+4)*SATT + rb + 8];
            uint32_t ah[4], al[4];
#pragma unroll
            for (int q = 0; q < 4; ++q) {
                uint32_t u;
                asm("cvt.rna.tf32.f32 %0, %1;" : "=r"(u) : "f"(av[q]));
                ah[q] = u;
                al[q] = __float_as_uint(av[q] - __uint_as_float(u));
            }
#pragma unroll
            for (int nt = 0; nt < 4; ++nt) {
                int cb = col0w + nt*8 + g;
                uint32_t bh0 = __float_as_uint(shh[(ks+tid)*WSTR + cb]);
                uint32_t bh1 = __float_as_uint(shh[(ks+tid+4)*WSTR + cb]);
                uint32_t bl0 = __float_as_uint(shl[(ks+tid)*WSTR + cb]);
                uint32_t bl1 = __float_as_uint(shl[(ks+tid+4)*WSTR + cb]);
                MMA_TF32(cacc[nt], ah, bh0, bh1);   // hi*hi
                MMA_TF32(cacc[nt], ah, bl0, bl1);   // hi*lo
                MMA_TF32(cacc[nt], al, bh0, bh1);   // lo*hi
            }
        }
        __syncthreads();
    }
#undef ISSUE_H

    if (last) {
        // fused mean partials: reduce relu over the block's 32 rows per column
        float* graph = g_zbuf + GRAPH_OFF;
#pragma unroll
        for (int nt = 0; nt < 4; ++nt) {
#pragma unroll
            for (int q2 = 0; q2 < 2; ++q2) {
                float p = fmaxf(cacc[nt][q2], 0.f) + fmaxf(cacc[nt][q2+2], 0.f);
#pragma unroll
                for (int off = 4; off <= 16; off <<= 1)
                    p += __shfl_xor_sync(0xffffffffu, p, off);
                if (g == 0) {
                    int col = c0 + col0w + nt*8 + 2*tid + q2;
                    atomicAdd(&graph[b*Hv + col], p);
                }
            }
        }
    } else {
        // transpose relu through smem (reuse att region: st[i][c], stride 68)
        __syncthreads();
        float* st = att;
        int rowA = row0w + g;
        int rowB = rowA + 8;
#pragma unroll
        for (int nt = 0; nt < 4; ++nt) {
            int colb = col0w + nt*8 + 2*tid;
            st[rowA*68 + colb]     = fmaxf(cacc[nt][0], 0.f);
            st[rowA*68 + colb + 1] = fmaxf(cacc[nt][1], 0.f);
            st[rowB*68 + colb]     = fmaxf(cacc[nt][2], 0.f);
            st[rowB*68 + colb + 1] = fmaxf(cacc[nt][3], 0.f);
        }
        __syncthreads();
        // thread t: channel ch = t&63, half = t>>6 -> 16 rows each, split store
        int ch   = t & 63;
        int half = t >> 6;
        size_t base = (size_t)(c0 + ch)*BN + b*Nv + i0 + half*16;
#pragma unroll
        for (int q = 0; q < 4; ++q) {
            int i = half*16 + 4*q;
            float4 hiv, lov;
            tf32split(st[(i+0)*68 + ch], hiv.x, lov.x);
            tf32split(st[(i+1)*68 + ch], hiv.y, lov.y);
            tf32split(st[(i+2)*68 + ch], hiv.z, lov.z);
            tf32split(st[(i+3)*68 + ch], hiv.w, lov.w);
            *reinterpret_cast<float4*>(&g_xhi[base + 4*q]) = hiv;
            *reinterpret_cast<float4*>(&g_xlo[base + 4*q]) = lov;
        }
    }
}

// ---------------------------------------------------------------------------
// K5: fused head. One block per batch element.
// ---------------------------------------------------------------------------
__global__ void k_head(const float* __restrict__ scaffold,
                       const float* __restrict__ W_sc,
                       const float* __restrict__ b_sc,
                       const float* __restrict__ gp_w1,
                       const float* __restrict__ gp_b1,
                       const float* __restrict__ gp_w2,
                       const float* __restrict__ gp_b2,
                       const float* __restrict__ out_w1,
                       const float* __restrict__ out_b1,
                       const float* __restrict__ out_w2,
                       const float* __restrict__ out_b2,
                       float* __restrict__ out)
{
    int b = blockIdx.x, t = threadIdx.x;
    const float* graph = g_zbuf + GRAPH_OFF;
    __shared__ float scaf[Sv];
    __shared__ float grow[Hv];
    __shared__ float sc[Hv];
    __shared__ float g1[128], sp1[128];
    __shared__ float c[128];
    __shared__ float hdn[128];

    if (t < Sv) scaf[t] = scaffold[b*Sv + t];
    grow[t] = graph[b*Hv + t] * (1.0f/Nv);
    __syncthreads();

    {
        float acc = b_sc[t];
#pragma unroll
        for (int k = 0; k < Sv; ++k)
            acc += scaf[k] * W_sc[k*Hv + t];
        sc[t] = acc;
    }
    __syncthreads();

    {
        int col = t & 127;
        const float* src = (t < 128) ? grow : sc;
        float acc = gp_b1[col];
#pragma unroll 4
        for (int k = 0; k < Hv; ++k)
            acc += src[k] * gp_w1[k*128 + col];
        acc = fmaxf(acc, 0.f);
        if (t < 128) g1[col] = acc; else sp1[col] = acc;
    }
    __syncthreads();

    if (t < 128) {
        int col = t & 63;
        const float* src = (t < 64) ? g1 : sp1;
        float acc = gp_b2[col];
#pragma unroll 4
        for (int k = 0; k < 128; ++k)
            acc += src[k] * gp_w2[k*64 + col];
        c[t] = fmaxf(acc, 0.f);
    }
    __syncthreads();

    if (t < 128) {
        float acc = out_b1[t];
#pragma unroll 4
        for (int k = 0; k < 128; ++k)
            acc += c[k] * out_w1[k*128 + t];
        hdn[t] = fmaxf(acc, 0.f);
    }
    __syncthreads();

    if (t < Tv) {
        float acc = out_b2[t];
#pragma unroll 4
        for (int k = 0; k < 128; ++k)
            acc += hdn[k] * out_w2[k*Tv + t];
        out[b*Tv + t] = acc;
    }
}

// ---------------------------------------------------------------------------
extern "C" void kernel_launch(void* const* d_in, const int* in_sizes, int n_in,
                              void* d_out, int out_size)
{
    const float* node_features     = (const float*)d_in[0];
    // d_in[1] = edge_features — unused by the reference
    const int*   adj_matrix        = (const int*)  d_in[2];
    const float* scaffold_features = (const float*)d_in[3];
    const float* W_node            = (const float*)d_in[4];
    const float* b_node            = (const float*)d_in[5];
    const float* gat_W             = (const float*)d_in[6];
    const float* gat_a             = (const float*)d_in[7];
    const float* W_sc              = (const float*)d_in[8];
    const float* b_sc              = (const float*)d_in[9];
    const float* gp_w1             = (const float*)d_in[10];
    const float* gp_b1             = (const float*)d_in[11];
    const float* gp_w2             = (const float*)d_in[12];
    const float* gp_b2             = (const float*)d_in[13];
    const float* out_w1            = (const float*)d_in[14];
    const float* out_b1            = (const float*)d_in[15];
    const float* out_w2            = (const float*)d_in[16];
    const float* out_b2            = (const float*)d_in[17];
    float* out = (float*)d_out;

    void* zp = nullptr;
    cudaGetSymbolAddress(&zp, g_zbuf);
    cudaMemsetAsync(zp, 0, (Lv*2*BN + Bv*Hv)*sizeof(float));

    k_split_w<<<Lv*Hv*Hv/256, 256>>>(gat_W);
    k_node_proj<<<BN/NP_ROWS, 256>>>(node_features, W_node, b_node);

    for (int l = 0; l < Lv; ++l) {
        dim3 pg(BN/32, Hv/64);                 // 128 x 4 = 512 blocks, 128 thr
        k_gat_proj<<<pg, 128>>>(gat_a + (size_t)l*2*Hv, l);
        dim3 ag(Nv/32, Hv/64, Bv);             // 4 x 4 x 32 = 512 blocks, 128 thr
        k_gat_agg<<<ag, 128>>>(adj_matrix, l, l == Lv-1);
    }

    k_head<<<Bv, 256>>>(scaffold_features, W_sc, b_sc,
                        gp_w1, gp_b1, gp_w2, gp_b2,
                        out_w1, out_b1, out_w2, out_b2, out);
}